// round 11
// baseline (speedup 1.0000x reference)
#include <cuda_runtime.h>
#include <cuda_fp16.h>
#include <math.h>

#define NN 500000
#define EE 16000000
#define TB 256

// ---- single aligned scratch blob -------------------------------------------
#define OFF_COUNTS 0ULL                      // int[NN]
#define OFF_ROW    2000000ULL                // int[NN+1]
#define OFF_CUR    4000128ULL                // int[NN]
#define OFF_DIS    6000128ULL                // float[NN]
#define OFF_BSUM   8000128ULL                // int[1024]
#define OFF_BOFF   8004224ULL                // int[1024]
#define OFF_CSR    8008320ULL                // int[EE]
#define OFF_H      72008320ULL               // half[NN*16]  16MB
#define OFF_G      88008320ULL               // half[NN*16]  16MB
#define OFF_H3     104008320ULL              // float[NN*4]   8MB
#define SCRATCH_BYTES 112008320ULL

__device__ __align__(128) unsigned char g_scratch[SCRATCH_BYTES];
__device__ int g_is64;   // 1 if edge_index is int64, 0 if int32

__device__ __forceinline__ int*    sc_counts() { return (int*)   (g_scratch + OFF_COUNTS); }
__device__ __forceinline__ int*    sc_row()    { return (int*)   (g_scratch + OFF_ROW); }
__device__ __forceinline__ int*    sc_cur()    { return (int*)   (g_scratch + OFF_CUR); }
__device__ __forceinline__ float*  sc_dis()    { return (float*) (g_scratch + OFF_DIS); }
__device__ __forceinline__ int*    sc_bsum()   { return (int*)   (g_scratch + OFF_BSUM); }
__device__ __forceinline__ int*    sc_boff()   { return (int*)   (g_scratch + OFF_BOFF); }
__device__ __forceinline__ int*    sc_csr()    { return (int*)   (g_scratch + OFF_CSR); }
__device__ __forceinline__ __half* sc_h()      { return (__half*)(g_scratch + OFF_H); }
__device__ __forceinline__ __half* sc_g()      { return (__half*)(g_scratch + OFF_G); }
__device__ __forceinline__ float*  sc_h3()     { return (float*) (g_scratch + OFF_H3); }

// ---------------- zero + dtype probe ----------------------------------------
__global__ void k_zero(const int* __restrict__ ei32, int n) {
    int i = blockIdx.x * blockDim.x + threadIdx.x;
    if (i < n) sc_counts()[i] = 0;
    if (i == 0) {
        int all_zero = 1;
        #pragma unroll 1
        for (int k = 0; k < 64; k++)
            if (ei32[2 * k + 1] != 0) { all_zero = 0; break; }
        g_is64 = all_zero;
    }
}

// ---- 4-edges-per-thread vector loaders --------------------------------------
struct Edge4 { int s[4]; int d[4]; };

__device__ __forceinline__ Edge4 load_edge4(const void* eiv, int E, int e0, int is64) {
    Edge4 r;
    if (is64) {
        const longlong2* ei = (const longlong2*)eiv;
        longlong2 s01 = __ldcs(&ei[e0 >> 1]);
        longlong2 s23 = __ldcs(&ei[(e0 >> 1) + 1]);
        longlong2 d01 = __ldcs(&ei[(E + e0) >> 1]);
        longlong2 d23 = __ldcs(&ei[((E + e0) >> 1) + 1]);
        long long ss[4] = { s01.x, s01.y, s23.x, s23.y };
        long long dd[4] = { d01.x, d01.y, d23.x, d23.y };
        #pragma unroll
        for (int k = 0; k < 4; k++) {
            r.s[k] = (int)ss[k]; r.d[k] = (int)dd[k];
            if ((unsigned long long)ss[k] >= (unsigned long long)NN ||
                (unsigned long long)dd[k] >= (unsigned long long)NN) { r.s[k] = -1; r.d[k] = -1; }
        }
    } else {
        const int4* ei = (const int4*)eiv;
        int4 sv = __ldcs(&ei[e0 >> 2]);
        int4 dv = __ldcs(&ei[(E + e0) >> 2]);
        int ss[4] = { sv.x, sv.y, sv.z, sv.w };
        int dd[4] = { dv.x, dv.y, dv.z, dv.w };
        #pragma unroll
        for (int k = 0; k < 4; k++) {
            r.s[k] = ss[k]; r.d[k] = dd[k];
            if ((unsigned)ss[k] >= (unsigned)NN || (unsigned)dd[k] >= (unsigned)NN) { r.s[k] = -1; r.d[k] = -1; }
        }
    }
    return r;
}

// ---------------- CSR build ---------------------------------------------------
__global__ void k_hist(const void* __restrict__ eiv, int E) {
    int t = blockIdx.x * blockDim.x + threadIdx.x;
    int e0 = t * 4;
    if (e0 >= E) return;
    Edge4 ed = load_edge4(eiv, E, e0, g_is64);
    #pragma unroll
    for (int k = 0; k < 4; k++)
        if (ed.d[k] >= 0) atomicAdd(&sc_counts()[ed.d[k]], 1);
}

__global__ void k_scan_block(int n) {
    __shared__ int sh[1024];
    int t = threadIdx.x;
    int i = blockIdx.x * 1024 + t;
    int v = (i < n) ? sc_counts()[i] : 0;
    sh[t] = v;
    __syncthreads();
    for (int off = 1; off < 1024; off <<= 1) {
        int a = (t >= off) ? sh[t - off] : 0;
        __syncthreads();
        sh[t] += a;
        __syncthreads();
    }
    if (i < n) sc_row()[i] = sh[t] - v;
    if (t == 1023) sc_bsum()[blockIdx.x] = sh[1023];
}

__global__ void k_scan_top(int nb, int n) {
    __shared__ int sh[1024];
    int t = threadIdx.x;
    int v = (t < nb) ? sc_bsum()[t] : 0;
    sh[t] = v;
    __syncthreads();
    for (int off = 1; off < 1024; off <<= 1) {
        int a = (t >= off) ? sh[t - off] : 0;
        __syncthreads();
        sh[t] += a;
        __syncthreads();
    }
    sc_boff()[t] = sh[t] - v;
    if (t == 1023) sc_row()[n] = sh[1023];
}

// ------------- pack/unpack helpers -------------------------------------------
__device__ __forceinline__ uint4 pack8(const float* o) {
    __half2 p0 = __floats2half2_rn(o[0], o[1]);
    __half2 p1 = __floats2half2_rn(o[2], o[3]);
    __half2 p2 = __floats2half2_rn(o[4], o[5]);
    __half2 p3 = __floats2half2_rn(o[6], o[7]);
    uint4 u;
    u.x = *(unsigned int*)&p0; u.y = *(unsigned int*)&p1;
    u.z = *(unsigned int*)&p2; u.w = *(unsigned int*)&p3;
    return u;
}

__device__ __forceinline__ void acc8(float* acc, uint4 v) {
    float2 f;
    f = __half22float2(*(__half2*)&v.x); acc[0] += f.x; acc[1] += f.y;
    f = __half22float2(*(__half2*)&v.y); acc[2] += f.x; acc[3] += f.y;
    f = __half22float2(*(__half2*)&v.z); acc[4] += f.x; acc[5] += f.y;
    f = __half22float2(*(__half2*)&v.w); acc[6] += f.x; acc[7] += f.y;
}

// ------ fused finish + layer1 transform: row/cur/dis + h1'=(x@W1)*dis --------
__global__ void __launch_bounds__(TB)
k_finish_t1(const float* __restrict__ x, const float* __restrict__ W, int n) {
    __shared__ float Ws[225];
    for (int t = threadIdx.x; t < 225; t += blockDim.x) Ws[t] = W[t];
    __syncthreads();
    int i = blockIdx.x * blockDim.x + threadIdx.x;
    if (i >= n) return;

    int r = sc_row()[i] + sc_boff()[i >> 10];
    sc_row()[i] = r;
    sc_cur()[i] = r;
    float di = rsqrtf((float)(sc_counts()[i] + 1));
    sc_dis()[i] = di;

    float xv[15];
    #pragma unroll
    for (int k = 0; k < 15; k++) xv[k] = __ldcs(&x[(size_t)i * 15 + k]);
    float o[16];
    o[15] = 0.f;
    #pragma unroll
    for (int j = 0; j < 15; j++) {
        float s = 0.f;
        #pragma unroll
        for (int k = 0; k < 15; k++) s += xv[k] * Ws[k * 15 + j];
        o[j] = s * di;
    }
    uint4* outp = (uint4*)(sc_h() + (size_t)i * 16);
    outp[0] = pack8(o);
    outp[1] = pack8(o + 8);
}

// ---------------- edge scatter -------------------------------------------------
__global__ void k_scatter(const void* __restrict__ eiv, int E) {
    int t = blockIdx.x * blockDim.x + threadIdx.x;
    int e0 = t * 4;
    if (e0 >= E) return;
    Edge4 ed = load_edge4(eiv, E, e0, g_is64);
    #pragma unroll
    for (int k = 0; k < 4; k++) {
        if (ed.d[k] >= 0) {
            int p = atomicAdd(&sc_cur()[ed.d[k]], 1);
            sc_csr()[p] = ed.s[k];
        }
    }
}

// ------- 2-lanes-per-node fp16 aggregation + fused next-layer transform -------
// Gather loop unrolled x8 (8 outstanding L2 gathers/lane -> BW-bound regime).
// Pair exchange via shfl_xor (NO block barrier -> no cross-pair imbalance
// coupling; round-9 lesson: permutations hurt, barriers were the real cost).
template <int FOUT>
__global__ void __launch_bounds__(TB)
k_agg2(const float* __restrict__ bias, const float* __restrict__ Wn, int n) {
    __shared__ float Ws[16 * 16];
    __shared__ float bs[16];

    for (int t = threadIdx.x; t < 256; t += blockDim.x) Ws[t] = 0.f;
    if (threadIdx.x < 16) bs[threadIdx.x] = 0.f;
    __syncthreads();
    if (FOUT == 15) {
        for (int t = threadIdx.x; t < 225; t += blockDim.x)
            Ws[(t / 15) * 16 + (t % 15)] = Wn[t];
    } else {
        for (int t = threadIdx.x; t < 60; t += blockDim.x) Ws[t] = Wn[t];
    }
    if (threadIdx.x < 15) bs[threadIdx.x] = bias[threadIdx.x];
    __syncthreads();

    int gidx = threadIdx.x >> 1;
    int c    = threadIdx.x & 1;
    int i    = blockIdx.x * (TB / 2) + gidx;
    if (i >= n) return;

    const uint4* hb = (const uint4*)((FOUT == 15) ? sc_h() : sc_g());
    const int* csr = sc_csr();

    float acc[8];
    #pragma unroll
    for (int t = 0; t < 8; t++) acc[t] = 0.f;

    int beg = sc_row()[i], end = sc_row()[i + 1];
    int j = beg;
    for (; j + 8 <= end; j += 8) {
        int s0 = __ldcs(&csr[j + 0]);
        int s1 = __ldcs(&csr[j + 1]);
        int s2 = __ldcs(&csr[j + 2]);
        int s3 = __ldcs(&csr[j + 3]);
        int s4 = __ldcs(&csr[j + 4]);
        int s5 = __ldcs(&csr[j + 5]);
        int s6 = __ldcs(&csr[j + 6]);
        int s7 = __ldcs(&csr[j + 7]);
        uint4 v0 = hb[(size_t)s0 * 2 + c];
        uint4 v1 = hb[(size_t)s1 * 2 + c];
        uint4 v2 = hb[(size_t)s2 * 2 + c];
        uint4 v3 = hb[(size_t)s3 * 2 + c];
        uint4 v4 = hb[(size_t)s4 * 2 + c];
        uint4 v5 = hb[(size_t)s5 * 2 + c];
        uint4 v6 = hb[(size_t)s6 * 2 + c];
        uint4 v7 = hb[(size_t)s7 * 2 + c];
        acc8(acc, v0); acc8(acc, v1); acc8(acc, v2); acc8(acc, v3);
        acc8(acc, v4); acc8(acc, v5); acc8(acc, v6); acc8(acc, v7);
    }
    for (; j + 2 <= end; j += 2) {
        int s0 = __ldcs(&csr[j + 0]);
        int s1 = __ldcs(&csr[j + 1]);
        uint4 v0 = hb[(size_t)s0 * 2 + c];
        uint4 v1 = hb[(size_t)s1 * 2 + c];
        acc8(acc, v0); acc8(acc, v1);
    }
    for (; j < end; j++) {
        int s = __ldcs(&csr[j]);
        acc8(acc, hb[(size_t)s * 2 + c]);
    }
    acc8(acc, hb[(size_t)i * 2 + c]);        // self-loop

    float di = sc_dis()[i];
    int k0 = c * 8;
    float y[16];
    #pragma unroll
    for (int t = 0; t < 8; t++)
        y[k0 + t] = fmaxf(acc[t] * di + bs[k0 + t], 0.f);
    // exchange the 8 y-values with partner lane (xor 1) — no block barrier
    int ko = 8 - k0;   // partner's base: c==0 -> 8, c==1 -> 0
    #pragma unroll
    for (int t = 0; t < 8; t++)
        y[ko + t] = __shfl_xor_sync(0xFFFFFFFFu, y[k0 + t], 1);

    if (FOUT == 15) {
        int j0 = c * 8;
        float o[8];
        #pragma unroll
        for (int t = 0; t < 8; t++) o[t] = 0.f;
        #pragma unroll
        for (int k = 0; k < 15; k++) {
            float yk = y[k];
            #pragma unroll
            for (int t = 0; t < 8; t++)
                o[t] += yk * Ws[k * 16 + j0 + t];
        }
        #pragma unroll
        for (int t = 0; t < 8; t++) o[t] *= di;
        ((uint4*)sc_g())[(size_t)i * 2 + c] = pack8(o);
    } else {
        int j0 = c * 2;
        float o0 = 0.f, o1 = 0.f;
        #pragma unroll
        for (int k = 0; k < 15; k++) {
            float yk = y[k];
            o0 += yk * Ws[k * 4 + j0 + 0];
            o1 += yk * Ws[k * 4 + j0 + 1];
        }
        float2* outp = (float2*)(sc_h3() + (size_t)i * 4 + j0);
        *outp = make_float2(o0 * di, o1 * di);
    }
}

// ---------------- final layer aggregation --------------------------------------
__global__ void __launch_bounds__(TB)
k_agg_final(const float* __restrict__ bias, float* __restrict__ out, int n) {
    int i = blockIdx.x * blockDim.x + threadIdx.x;
    if (i >= n) return;
    const float4* hb = (const float4*)sc_h3();
    const int* csr = sc_csr();
    float ax = 0.f, ay = 0.f, az = 0.f, aw = 0.f;
    int beg = sc_row()[i], end = sc_row()[i + 1];
    int j = beg;
    for (; j + 8 <= end; j += 8) {
        int s0 = __ldcs(&csr[j + 0]);
        int s1 = __ldcs(&csr[j + 1]);
        int s2 = __ldcs(&csr[j + 2]);
        int s3 = __ldcs(&csr[j + 3]);
        int s4 = __ldcs(&csr[j + 4]);
        int s5 = __ldcs(&csr[j + 5]);
        int s6 = __ldcs(&csr[j + 6]);
        int s7 = __ldcs(&csr[j + 7]);
        float4 v0 = hb[s0];
        float4 v1 = hb[s1];
        float4 v2 = hb[s2];
        float4 v3 = hb[s3];
        float4 v4 = hb[s4];
        float4 v5 = hb[s5];
        float4 v6 = hb[s6];
        float4 v7 = hb[s7];
        ax += v0.x + v1.x + v2.x + v3.x + v4.x + v5.x + v6.x + v7.x;
        ay += v0.y + v1.y + v2.y + v3.y + v4.y + v5.y + v6.y + v7.y;
        az += v0.z + v1.z + v2.z + v3.z + v4.z + v5.z + v6.z + v7.z;
        aw += v0.w + v1.w + v2.w + v3.w + v4.w + v5.w + v6.w + v7.w;
    }
    for (; j < end; j++) {
        int s = __ldcs(&csr[j]);
        float4 v = hb[s];
        ax += v.x; ay += v.y; az += v.z; aw += v.w;
    }
    float4 v = hb[i];   // self-loop
    ax += v.x; ay += v.y; az += v.z; aw += v.w;
    float di = sc_dis()[i];
    float b0 = bias[0], b1 = bias[1], b2 = bias[2], b3 = bias[3];
    ((float4*)out)[i] = make_float4(ax * di + b0, ay * di + b1,
                                    az * di + b2, aw * di + b3);
}

// ---------------- launch --------------------------------------------------------
extern "C" void kernel_launch(void* const* d_in, const int* in_sizes, int n_in,
                              void* d_out, int out_size) {
    const float* x = nullptr; const void* ei = nullptr;
    const float* W1 = nullptr; const float* W2 = nullptr;
    const float* b1 = nullptr; const float* b2 = nullptr;
    const float* W3 = nullptr; const float* b3 = nullptr;
    long long E_ll = 0;
    for (int i = 0; i < n_in; i++) {
        long long sz = in_sizes[i];
        if (sz == 7500000)            x = (const float*)d_in[i];
        else if (sz == 32000000)    { ei = d_in[i]; E_ll = sz / 2; }
        else if (sz == 225)         { if (!W1) W1 = (const float*)d_in[i]; else W2 = (const float*)d_in[i]; }
        else if (sz == 15)          { if (!b1) b1 = (const float*)d_in[i]; else b2 = (const float*)d_in[i]; }
        else if (sz == 60)            W3 = (const float*)d_in[i];
        else if (sz == 4)             b3 = (const float*)d_in[i];
    }
    if (!x)  x  = (const float*)d_in[0];
    if (!ei) { ei = d_in[1]; E_ll = in_sizes[1] / 2; }
    if (!W1) W1 = (const float*)d_in[3];
    if (!b1) b1 = (const float*)d_in[4];
    if (!W2) W2 = (const float*)d_in[5];
    if (!b2) b2 = (const float*)d_in[6];
    if (!W3) W3 = (const float*)d_in[7];
    if (!b3) b3 = (const float*)d_in[8];

    float* out = (float*)d_out;
    int n = NN;
    int E = (int)E_ll;

    int gbN  = (n + TB - 1) / TB;
    int gbE4 = (E / 4 + TB - 1) / TB;
    int nb   = (n + 1023) / 1024;
    int gbN2 = (n + (TB / 2) - 1) / (TB / 2);

    k_zero<<<gbN, TB>>>((const int*)ei, n);
    k_hist<<<gbE4, TB>>>(ei, E);
    k_scan_block<<<nb, 1024>>>(n);
    k_scan_top<<<1, 1024>>>(nb, n);
    k_finish_t1<<<gbN, TB>>>(x, W1, n);
    k_scatter<<<gbE4, TB>>>(ei, E);

    k_agg2<15><<<gbN2, TB>>>(b1, W2, n);
    k_agg2<4><<<gbN2, TB>>>(b2, W3, n);
    k_agg_final<<<gbN, TB>>>(b3, out, n);
}

// round 12
// speedup vs baseline: 1.0033x; 1.0033x over previous
#include <cuda_runtime.h>
#include <cuda_fp16.h>
#include <math.h>

#define NN 500000
#define EE 16000000
#define TB 256

// ---- single aligned scratch blob -------------------------------------------
#define OFF_COUNTS 0ULL                      // int[NN]
#define OFF_ROW    2000000ULL                // int[NN+1]
#define OFF_CUR    4000128ULL                // int[NN]
#define OFF_DIS    6000128ULL                // float[NN]
#define OFF_BSUM   8000128ULL                // int[1024]
#define OFF_BOFF   8004224ULL                // int[1024]
#define OFF_CSR    8008320ULL                // int[EE]
#define OFF_H      72008320ULL               // half[NN*16]  16MB
#define OFF_G      88008320ULL               // half[NN*16]  16MB
#define OFF_H3     104008320ULL              // float[NN*4]   8MB
#define SCRATCH_BYTES 112008320ULL

__device__ __align__(128) unsigned char g_scratch[SCRATCH_BYTES];
__device__ int g_is64;   // 1 if edge_index is int64, 0 if int32

__device__ __forceinline__ int*    sc_counts() { return (int*)   (g_scratch + OFF_COUNTS); }
__device__ __forceinline__ int*    sc_row()    { return (int*)   (g_scratch + OFF_ROW); }
__device__ __forceinline__ int*    sc_cur()    { return (int*)   (g_scratch + OFF_CUR); }
__device__ __forceinline__ float*  sc_dis()    { return (float*) (g_scratch + OFF_DIS); }
__device__ __forceinline__ int*    sc_bsum()   { return (int*)   (g_scratch + OFF_BSUM); }
__device__ __forceinline__ int*    sc_boff()   { return (int*)   (g_scratch + OFF_BOFF); }
__device__ __forceinline__ int*    sc_csr()    { return (int*)   (g_scratch + OFF_CSR); }
__device__ __forceinline__ __half* sc_h()      { return (__half*)(g_scratch + OFF_H); }
__device__ __forceinline__ __half* sc_g()      { return (__half*)(g_scratch + OFF_G); }
__device__ __forceinline__ float*  sc_h3()     { return (float*) (g_scratch + OFF_H3); }

// ---------------- zero + dtype probe ----------------------------------------
__global__ void k_zero(const int* __restrict__ ei32, int n) {
    int i = blockIdx.x * blockDim.x + threadIdx.x;
    if (i < n) sc_counts()[i] = 0;
    if (i == 0) {
        int all_zero = 1;
        #pragma unroll 1
        for (int k = 0; k < 64; k++)
            if (ei32[2 * k + 1] != 0) { all_zero = 0; break; }
        g_is64 = all_zero;
    }
}

// ---- 4-edges-per-thread vector loaders --------------------------------------
struct Edge4 { int s[4]; int d[4]; };

__device__ __forceinline__ Edge4 load_edge4(const void* eiv, int E, int e0, int is64) {
    Edge4 r;
    if (is64) {
        const longlong2* ei = (const longlong2*)eiv;
        longlong2 s01 = __ldcs(&ei[e0 >> 1]);
        longlong2 s23 = __ldcs(&ei[(e0 >> 1) + 1]);
        longlong2 d01 = __ldcs(&ei[(E + e0) >> 1]);
        longlong2 d23 = __ldcs(&ei[((E + e0) >> 1) + 1]);
        long long ss[4] = { s01.x, s01.y, s23.x, s23.y };
        long long dd[4] = { d01.x, d01.y, d23.x, d23.y };
        #pragma unroll
        for (int k = 0; k < 4; k++) {
            r.s[k] = (int)ss[k]; r.d[k] = (int)dd[k];
            if ((unsigned long long)ss[k] >= (unsigned long long)NN ||
                (unsigned long long)dd[k] >= (unsigned long long)NN) { r.s[k] = -1; r.d[k] = -1; }
        }
    } else {
        const int4* ei = (const int4*)eiv;
        int4 sv = __ldcs(&ei[e0 >> 2]);
        int4 dv = __ldcs(&ei[(E + e0) >> 2]);
        int ss[4] = { sv.x, sv.y, sv.z, sv.w };
        int dd[4] = { dv.x, dv.y, dv.z, dv.w };
        #pragma unroll
        for (int k = 0; k < 4; k++) {
            r.s[k] = ss[k]; r.d[k] = dd[k];
            if ((unsigned)ss[k] >= (unsigned)NN || (unsigned)dd[k] >= (unsigned)NN) { r.s[k] = -1; r.d[k] = -1; }
        }
    }
    return r;
}

// ---------------- CSR build ---------------------------------------------------
__global__ void k_hist(const void* __restrict__ eiv, int E) {
    int t = blockIdx.x * blockDim.x + threadIdx.x;
    int e0 = t * 4;
    if (e0 >= E) return;
    Edge4 ed = load_edge4(eiv, E, e0, g_is64);
    #pragma unroll
    for (int k = 0; k < 4; k++)
        if (ed.d[k] >= 0) atomicAdd(&sc_counts()[ed.d[k]], 1);
}

__global__ void k_scan_block(int n) {
    __shared__ int sh[1024];
    int t = threadIdx.x;
    int i = blockIdx.x * 1024 + t;
    int v = (i < n) ? sc_counts()[i] : 0;
    sh[t] = v;
    __syncthreads();
    for (int off = 1; off < 1024; off <<= 1) {
        int a = (t >= off) ? sh[t - off] : 0;
        __syncthreads();
        sh[t] += a;
        __syncthreads();
    }
    if (i < n) sc_row()[i] = sh[t] - v;
    if (t == 1023) sc_bsum()[blockIdx.x] = sh[1023];
}

__global__ void k_scan_top(int nb, int n) {
    __shared__ int sh[1024];
    int t = threadIdx.x;
    int v = (t < nb) ? sc_bsum()[t] : 0;
    sh[t] = v;
    __syncthreads();
    for (int off = 1; off < 1024; off <<= 1) {
        int a = (t >= off) ? sh[t - off] : 0;
        __syncthreads();
        sh[t] += a;
        __syncthreads();
    }
    sc_boff()[t] = sh[t] - v;
    if (t == 1023) sc_row()[n] = sh[1023];
}

// ------------- pack/unpack helpers -------------------------------------------
__device__ __forceinline__ uint4 pack8(const float* o) {
    __half2 p0 = __floats2half2_rn(o[0], o[1]);
    __half2 p1 = __floats2half2_rn(o[2], o[3]);
    __half2 p2 = __floats2half2_rn(o[4], o[5]);
    __half2 p3 = __floats2half2_rn(o[6], o[7]);
    uint4 u;
    u.x = *(unsigned int*)&p0; u.y = *(unsigned int*)&p1;
    u.z = *(unsigned int*)&p2; u.w = *(unsigned int*)&p3;
    return u;
}

__device__ __forceinline__ void acc8(float* acc, uint4 v) {
    float2 f;
    f = __half22float2(*(__half2*)&v.x); acc[0] += f.x; acc[1] += f.y;
    f = __half22float2(*(__half2*)&v.y); acc[2] += f.x; acc[3] += f.y;
    f = __half22float2(*(__half2*)&v.z); acc[4] += f.x; acc[5] += f.y;
    f = __half22float2(*(__half2*)&v.w); acc[6] += f.x; acc[7] += f.y;
}

// ------ fused finish + layer1 transform: row/cur/dis + h1'=(x@W1)*dis --------
__global__ void __launch_bounds__(TB)
k_finish_t1(const float* __restrict__ x, const float* __restrict__ W, int n) {
    __shared__ float Ws[225];
    for (int t = threadIdx.x; t < 225; t += blockDim.x) Ws[t] = W[t];
    __syncthreads();
    int i = blockIdx.x * blockDim.x + threadIdx.x;
    if (i >= n) return;

    int r = sc_row()[i] + sc_boff()[i >> 10];
    sc_row()[i] = r;
    sc_cur()[i] = r;
    float di = rsqrtf((float)(sc_counts()[i] + 1));
    sc_dis()[i] = di;

    float xv[15];
    #pragma unroll
    for (int k = 0; k < 15; k++) xv[k] = __ldcs(&x[(size_t)i * 15 + k]);
    float o[16];
    o[15] = 0.f;
    #pragma unroll
    for (int j = 0; j < 15; j++) {
        float s = 0.f;
        #pragma unroll
        for (int k = 0; k < 15; k++) s += xv[k] * Ws[k * 15 + j];
        o[j] = s * di;
    }
    uint4* outp = (uint4*)(sc_h() + (size_t)i * 16);
    outp[0] = pack8(o);
    outp[1] = pack8(o + 8);
}

// ---------------- edge scatter -------------------------------------------------
__global__ void k_scatter(const void* __restrict__ eiv, int E) {
    int t = blockIdx.x * blockDim.x + threadIdx.x;
    int e0 = t * 4;
    if (e0 >= E) return;
    Edge4 ed = load_edge4(eiv, E, e0, g_is64);
    #pragma unroll
    for (int k = 0; k < 4; k++) {
        if (ed.d[k] >= 0) {
            int p = atomicAdd(&sc_cur()[ed.d[k]], 1);
            sc_csr()[p] = ed.s[k];
        }
    }
}

// ------- 2-lanes-per-node fp16 aggregation + fused next-layer transform -------
// Gather loop unrolled x8 (8 outstanding L2 gathers/lane -> BW-bound regime).
// Pair exchange via shfl_xor (NO block barrier -> no cross-pair imbalance
// coupling; round-9 lesson: permutations hurt, barriers were the real cost).
template <int FOUT>
__global__ void __launch_bounds__(TB)
k_agg2(const float* __restrict__ bias, const float* __restrict__ Wn, int n) {
    __shared__ float Ws[16 * 16];
    __shared__ float bs[16];

    for (int t = threadIdx.x; t < 256; t += blockDim.x) Ws[t] = 0.f;
    if (threadIdx.x < 16) bs[threadIdx.x] = 0.f;
    __syncthreads();
    if (FOUT == 15) {
        for (int t = threadIdx.x; t < 225; t += blockDim.x)
            Ws[(t / 15) * 16 + (t % 15)] = Wn[t];
    } else {
        for (int t = threadIdx.x; t < 60; t += blockDim.x) Ws[t] = Wn[t];
    }
    if (threadIdx.x < 15) bs[threadIdx.x] = bias[threadIdx.x];
    __syncthreads();

    int gidx = threadIdx.x >> 1;
    int c    = threadIdx.x & 1;
    int i    = blockIdx.x * (TB / 2) + gidx;
    if (i >= n) return;

    const uint4* hb = (const uint4*)((FOUT == 15) ? sc_h() : sc_g());
    const int* csr = sc_csr();

    float acc[8];
    #pragma unroll
    for (int t = 0; t < 8; t++) acc[t] = 0.f;

    int beg = sc_row()[i], end = sc_row()[i + 1];
    int j = beg;
    for (; j + 8 <= end; j += 8) {
        int s0 = __ldcs(&csr[j + 0]);
        int s1 = __ldcs(&csr[j + 1]);
        int s2 = __ldcs(&csr[j + 2]);
        int s3 = __ldcs(&csr[j + 3]);
        int s4 = __ldcs(&csr[j + 4]);
        int s5 = __ldcs(&csr[j + 5]);
        int s6 = __ldcs(&csr[j + 6]);
        int s7 = __ldcs(&csr[j + 7]);
        uint4 v0 = hb[(size_t)s0 * 2 + c];
        uint4 v1 = hb[(size_t)s1 * 2 + c];
        uint4 v2 = hb[(size_t)s2 * 2 + c];
        uint4 v3 = hb[(size_t)s3 * 2 + c];
        uint4 v4 = hb[(size_t)s4 * 2 + c];
        uint4 v5 = hb[(size_t)s5 * 2 + c];
        uint4 v6 = hb[(size_t)s6 * 2 + c];
        uint4 v7 = hb[(size_t)s7 * 2 + c];
        acc8(acc, v0); acc8(acc, v1); acc8(acc, v2); acc8(acc, v3);
        acc8(acc, v4); acc8(acc, v5); acc8(acc, v6); acc8(acc, v7);
    }
    for (; j + 2 <= end; j += 2) {
        int s0 = __ldcs(&csr[j + 0]);
        int s1 = __ldcs(&csr[j + 1]);
        uint4 v0 = hb[(size_t)s0 * 2 + c];
        uint4 v1 = hb[(size_t)s1 * 2 + c];
        acc8(acc, v0); acc8(acc, v1);
    }
    for (; j < end; j++) {
        int s = __ldcs(&csr[j]);
        acc8(acc, hb[(size_t)s * 2 + c]);
    }
    acc8(acc, hb[(size_t)i * 2 + c]);        // self-loop

    float di = sc_dis()[i];
    int k0 = c * 8;
    float y[16];
    #pragma unroll
    for (int t = 0; t < 8; t++)
        y[k0 + t] = fmaxf(acc[t] * di + bs[k0 + t], 0.f);
    // exchange the 8 y-values with partner lane (xor 1) — no block barrier
    int ko = 8 - k0;   // partner's base: c==0 -> 8, c==1 -> 0
    #pragma unroll
    for (int t = 0; t < 8; t++)
        y[ko + t] = __shfl_xor_sync(0xFFFFFFFFu, y[k0 + t], 1);

    if (FOUT == 15) {
        int j0 = c * 8;
        float o[8];
        #pragma unroll
        for (int t = 0; t < 8; t++) o[t] = 0.f;
        #pragma unroll
        for (int k = 0; k < 15; k++) {
            float yk = y[k];
            #pragma unroll
            for (int t = 0; t < 8; t++)
                o[t] += yk * Ws[k * 16 + j0 + t];
        }
        #pragma unroll
        for (int t = 0; t < 8; t++) o[t] *= di;
        ((uint4*)sc_g())[(size_t)i * 2 + c] = pack8(o);
    } else {
        int j0 = c * 2;
        float o0 = 0.f, o1 = 0.f;
        #pragma unroll
        for (int k = 0; k < 15; k++) {
            float yk = y[k];
            o0 += yk * Ws[k * 4 + j0 + 0];
            o1 += yk * Ws[k * 4 + j0 + 1];
        }
        float2* outp = (float2*)(sc_h3() + (size_t)i * 4 + j0);
        *outp = make_float2(o0 * di, o1 * di);
    }
}

// ---------------- final layer aggregation --------------------------------------
__global__ void __launch_bounds__(TB)
k_agg_final(const float* __restrict__ bias, float* __restrict__ out, int n) {
    int i = blockIdx.x * blockDim.x + threadIdx.x;
    if (i >= n) return;
    const float4* hb = (const float4*)sc_h3();
    const int* csr = sc_csr();
    float ax = 0.f, ay = 0.f, az = 0.f, aw = 0.f;
    int beg = sc_row()[i], end = sc_row()[i + 1];
    int j = beg;
    for (; j + 8 <= end; j += 8) {
        int s0 = __ldcs(&csr[j + 0]);
        int s1 = __ldcs(&csr[j + 1]);
        int s2 = __ldcs(&csr[j + 2]);
        int s3 = __ldcs(&csr[j + 3]);
        int s4 = __ldcs(&csr[j + 4]);
        int s5 = __ldcs(&csr[j + 5]);
        int s6 = __ldcs(&csr[j + 6]);
        int s7 = __ldcs(&csr[j + 7]);
        float4 v0 = hb[s0];
        float4 v1 = hb[s1];
        float4 v2 = hb[s2];
        float4 v3 = hb[s3];
        float4 v4 = hb[s4];
        float4 v5 = hb[s5];
        float4 v6 = hb[s6];
        float4 v7 = hb[s7];
        ax += v0.x + v1.x + v2.x + v3.x + v4.x + v5.x + v6.x + v7.x;
        ay += v0.y + v1.y + v2.y + v3.y + v4.y + v5.y + v6.y + v7.y;
        az += v0.z + v1.z + v2.z + v3.z + v4.z + v5.z + v6.z + v7.z;
        aw += v0.w + v1.w + v2.w + v3.w + v4.w + v5.w + v6.w + v7.w;
    }
    for (; j < end; j++) {
        int s = __ldcs(&csr[j]);
        float4 v = hb[s];
        ax += v.x; ay += v.y; az += v.z; aw += v.w;
    }
    float4 v = hb[i];   // self-loop
    ax += v.x; ay += v.y; az += v.z; aw += v.w;
    float di = sc_dis()[i];
    float b0 = bias[0], b1 = bias[1], b2 = bias[2], b3 = bias[3];
    ((float4*)out)[i] = make_float4(ax * di + b0, ay * di + b1,
                                    az * di + b2, aw * di + b3);
}

// ---------------- launch --------------------------------------------------------
extern "C" void kernel_launch(void* const* d_in, const int* in_sizes, int n_in,
                              void* d_out, int out_size) {
    const float* x = nullptr; const void* ei = nullptr;
    const float* W1 = nullptr; const float* W2 = nullptr;
    const float* b1 = nullptr; const float* b2 = nullptr;
    const float* W3 = nullptr; const float* b3 = nullptr;
    long long E_ll = 0;
    for (int i = 0; i < n_in; i++) {
        long long sz = in_sizes[i];
        if (sz == 7500000)            x = (const float*)d_in[i];
        else if (sz == 32000000)    { ei = d_in[i]; E_ll = sz / 2; }
        else if (sz == 225)         { if (!W1) W1 = (const float*)d_in[i]; else W2 = (const float*)d_in[i]; }
        else if (sz == 15)          { if (!b1) b1 = (const float*)d_in[i]; else b2 = (const float*)d_in[i]; }
        else if (sz == 60)            W3 = (const float*)d_in[i];
        else if (sz == 4)             b3 = (const float*)d_in[i];
    }
    if (!x)  x  = (const float*)d_in[0];
    if (!ei) { ei = d_in[1]; E_ll = in_sizes[1] / 2; }
    if (!W1) W1 = (const float*)d_in[3];
    if (!b1) b1 = (const float*)d_in[4];
    if (!W2) W2 = (const float*)d_in[5];
    if (!b2) b2 = (const float*)d_in[6];
    if (!W3) W3 = (const float*)d_in[7];
    if (!b3) b3 = (const float*)d_in[8];

    float* out = (float*)d_out;
    int n = NN;
    int E = (int)E_ll;

    int gbN  = (n + TB - 1) / TB;
    int gbE4 = (E / 4 + TB - 1) / TB;
    int nb   = (n + 1023) / 1024;
    int gbN2 = (n + (TB / 2) - 1) / (TB / 2);

    k_zero<<<gbN, TB>>>((const int*)ei, n);
    k_hist<<<gbE4, TB>>>(ei, E);
    k_scan_block<<<nb, 1024>>>(n);
    k_scan_top<<<1, 1024>>>(nb, n);
    k_finish_t1<<<gbN, TB>>>(x, W1, n);
    k_scatter<<<gbE4, TB>>>(ei, E);

    k_agg2<15><<<gbN2, TB>>>(b1, W2, n);
    k_agg2<4><<<gbN2, TB>>>(b2, W3, n);
    k_agg_final<<<gbN, TB>>>(b3, out, n);
}